// round 15
// baseline (speedup 1.0000x reference)
#include <cuda_runtime.h>

#define HIDDEN    128
#define MAX_NODES 100000
#define NCOMBINE_BLOCKS 33     // 33 * 8 warps = 264 >= 258 combine tasks
#define NFLAGS    148

// Scratch (device globals; allocation is forbidden).
// Gap form: softmax over 2 classes depends only on l0-l1, so per node keep
//   gs[n] = n·dA,  gd[n] = n·dB,  dA/dB = W1 halves @ (w2_0 - w2_1).
__device__ float  g_GS[MAX_NODES];
__device__ float  g_GD[MAX_NODES];
__device__ float4 g_dAv[32], g_dBv[32];   // dA, dB as 32 x float4
__device__ float  g_gapb;                 // b1·(w2_0-w2_1) + b2_0 - b2_1
__device__ int    g_is64;
__device__ int    g_done;                 // combine-phase completion counter
__device__ int    g_flags[NFLAGS * 32];   // release flag mirrored per 128B line

// ---------------------------------------------------------------------------
// Fused combine+node kernel.
//  Blocks 0..32 (wave-1 by construction): collapse both layers into the gap
//  direction (warp-per-row) + gap bias + dtype probe, then release via a
//  flag mirrored across 148 cache lines. All other blocks sleep (tid0-only,
//  NO memory traffic before the flag — R8 showed prefetch floods the memory
//  system and delays the combine blocks' own loads by ~4.5us).
//  After release: every block computes one 64-node chunk of gap projections
//  (8 nodes/warp, row loads front-batched). Streams 51.2 MB once.
// ---------------------------------------------------------------------------
__global__ void __launch_bounds__(256) fused_cn_kernel(
        const float* __restrict__ feat,
        const float* __restrict__ W1, const float* __restrict__ b1,
        const float* __restrict__ W2, const float* __restrict__ b2,
        const long long* __restrict__ edges_as_i64,
        int n_edges, int n_nodes)
{
    int tid  = threadIdx.x;
    int warp = tid >> 5;
    int lane = tid & 31;

    // ---- Phase A: combine (lowest-bid blocks; scheduled in wave 1) ----
    if (blockIdx.x < NCOMBINE_BLOCKS) {
        int gw = blockIdx.x * 8 + warp;
        if (gw < 256) {
            // d[i] = sum_k W1[i][k] * (W2[k][0]-W2[k][1]),  row i = gw
            int i = gw;
            float acc = 0.f;
            #pragma unroll
            for (int k = lane; k < 4 * HIDDEN; k += 32)
                acc += W1[i * (4 * HIDDEN) + k] * (W2[2 * k] - W2[2 * k + 1]);
            #pragma unroll
            for (int o = 16; o; o >>= 1) acc += __shfl_xor_sync(0xffffffffu, acc, o);
            if (lane == 0) {
                float* dst = (i < HIDDEN) ? (float*)g_dAv : (float*)g_dBv;
                dst[i & (HIDDEN - 1)] = acc;
            }
        } else if (gw == 256) {
            float acc = 0.f;
            #pragma unroll
            for (int k = lane; k < 4 * HIDDEN; k += 32)
                acc += b1[k] * (W2[2 * k] - W2[2 * k + 1]);
            #pragma unroll
            for (int o = 16; o; o >>= 1) acc += __shfl_xor_sync(0xffffffffu, acc, o);
            if (lane == 0) g_gapb = acc + b2[0] - b2[1];
        } else if (gw == 257) {
            // Dtype probe: an int32 buffer misread as int64 pairs fails the
            // [0, MAX_NODES) range check almost surely over 64 samples.
            int ok = 1;
            #pragma unroll
            for (int r = 0; r < 2; ++r) {
                int t = r * 32 + lane;
                if (t < n_edges) {
                    long long v = edges_as_i64[t];
                    if (v < 0 || v >= (long long)MAX_NODES) ok = 0;
                }
            }
            ok = __all_sync(0xffffffffu, ok);
            if (lane == 0) g_is64 = ok;
        }
        __syncthreads();
        if (tid == 0) {
            __threadfence();                               // publish dA/dB/bias
            if (atomicAdd(&g_done, 1) == NCOMBINE_BLOCKS - 1) {
                #pragma unroll 4
                for (int f = 0; f < NFLAGS; ++f)
                    *(volatile int*)&g_flags[f * 32] = 1;  // mirrored release
            }
        }
    }

    // ---- Wait: tid0-only sleep on this block's private flag line, with
    //      NO prior memory traffic from this block. ----
    if (tid == 0) {
        volatile int* f = &g_flags[(blockIdx.x % NFLAGS) * 32];
        while (*f == 0) __nanosleep(64);
        __threadfence();                                   // acquire
    }
    __syncthreads();

    // ---- Phase B: one 64-node chunk per block (8 nodes/warp) ----
    float4 wa = g_dAv[lane];
    float4 wb = g_dBv[lane];

    int node0 = blockIdx.x * 64 + warp * 8;
    float4 x[8];
    #pragma unroll
    for (int r = 0; r < 8; ++r) {
        int node = node0 + r;
        if (node < n_nodes)
            x[r] = reinterpret_cast<const float4*>(feat + (size_t)node * HIDDEN)[lane];
    }
    #pragma unroll
    for (int r = 0; r < 8; ++r) {
        int node = node0 + r;
        if (node >= n_nodes) break;
        float gs = x[r].x * wa.x + x[r].y * wa.y + x[r].z * wa.z + x[r].w * wa.w;
        float gd = x[r].x * wb.x + x[r].y * wb.y + x[r].z * wb.z + x[r].w * wb.w;
        #pragma unroll
        for (int o = 16; o; o >>= 1) {
            gs += __shfl_xor_sync(0xffffffffu, gs, o);
            gd += __shfl_xor_sync(0xffffffffu, gd, o);
        }
        if (lane == 0) {
            g_GS[node] = gs;
            g_GD[node] = gd;
        }
    }
}

// ---------------------------------------------------------------------------
// Edge kernel: 2 edges per thread; 4B gathers from two 400 KB L2-resident
// tables.  gap = gs[s]+gd[d]+gapb;  p1 = 1/(1+exp(gap)).
// Also resets the fused kernel's sync state for the next graph replay
// (stream-ordered: runs after fused_cn, before next replay's fused_cn).
// ---------------------------------------------------------------------------
__global__ void __launch_bounds__(256) edge_kernel(const void* __restrict__ edges,
                                                   float2* __restrict__ out,
                                                   int n_edges)
{
    if (blockIdx.x == 0) {
        if (threadIdx.x < NFLAGS) g_flags[threadIdx.x * 32] = 0;
        if (threadIdx.x == 255) g_done = 0;
    }

    int t = blockIdx.x * blockDim.x + threadIdx.x;
    int base = t * 2;
    if (base >= n_edges) return;

    float gapb = g_gapb;

    if (base + 2 <= n_edges) {
        int s0, s1, d0, d1;
        if (g_is64) {
            const longlong2* E = (const longlong2*)edges;
            longlong2 s = E[base >> 1];
            longlong2 d = E[(n_edges + base) >> 1];    // n_edges even here
            s0 = (int)s.x; s1 = (int)s.y; d0 = (int)d.x; d1 = (int)d.y;
        } else {
            const int2* E = (const int2*)edges;
            int2 s = E[base >> 1];
            int2 d = E[(n_edges + base) >> 1];
            s0 = s.x; s1 = s.y; d0 = d.x; d1 = d.y;
        }

        float gs0 = __ldg(&g_GS[s0]);
        float gs1 = __ldg(&g_GS[s1]);
        float gd0 = __ldg(&g_GD[d0]);
        float gd1 = __ldg(&g_GD[d1]);

        float p0 = 1.0f / (1.0f + __expf(gs0 + gd0 + gapb));
        float p1 = 1.0f / (1.0f + __expf(gs1 + gd1 + gapb));

        *(float4*)(out + base) = make_float4(1.0f - p0, p0, 1.0f - p1, p1);
    } else {
        int e = n_edges - 1;                            // odd tail
        int si, di;
        if (g_is64) {
            const long long* E = (const long long*)edges;
            si = (int)E[e]; di = (int)E[e + n_edges];
        } else {
            const int* E = (const int*)edges;
            si = E[e]; di = E[e + n_edges];
        }
        float p = 1.0f / (1.0f + __expf(__ldg(&g_GS[si]) + __ldg(&g_GD[di]) + gapb));
        out[e] = make_float2(1.0f - p, p);
    }
}

// ---------------------------------------------------------------------------
// Launch. metadata order:
//   0: node_features_after_gcn (float32, N_NODES*128)
//   1: edges                   (int64 or int32, 2*N_EDGES)
//   2: W1 (256*512)  3: b1 (512)  4: W2 (512*2)  5: b2 (2)
// ---------------------------------------------------------------------------
extern "C" void kernel_launch(void* const* d_in, const int* in_sizes, int n_in,
                              void* d_out, int out_size)
{
    const float* feat  = (const float*)d_in[0];
    const void*  edges = d_in[1];
    const float* W1    = (const float*)d_in[2];
    const float* b1    = (const float*)d_in[3];
    const float* W2    = (const float*)d_in[4];
    const float* b2    = (const float*)d_in[5];

    int n_nodes = in_sizes[0] / HIDDEN;
    if (n_nodes > MAX_NODES) n_nodes = MAX_NODES;
    int n_edges = in_sizes[1] / 2;

    int nblocks = (n_nodes + 63) / 64;
    if (nblocks < NCOMBINE_BLOCKS) nblocks = NCOMBINE_BLOCKS;

    fused_cn_kernel<<<nblocks, 256>>>(feat, W1, b1, W2, b2,
                                      (const long long*)edges, n_edges, n_nodes);

    int nthreads = (n_edges + 1) / 2;
    edge_kernel<<<(nthreads + 255) / 256, 256>>>(edges, (float2*)d_out, n_edges);
}

// round 16
// speedup vs baseline: 1.1937x; 1.1937x over previous
#include <cuda_runtime.h>

#define HIDDEN    128
#define MAX_NODES 100000

// Scratch (device globals; allocation is forbidden).
// Gap form: softmax over 2 classes depends only on l0-l1, so per node keep
//   gs[n] = n·dA,  gd[n] = n·dB,  dA/dB = W1 halves @ (w2_0 - w2_1).
__device__ float  g_GS[MAX_NODES];
__device__ float  g_GD[MAX_NODES];
__device__ float4 g_dAv[32], g_dBv[32];   // dA, dB as 32 x float4
__device__ float  g_gapb;                 // b1·(w2_0-w2_1) + b2_0 - b2_1
__device__ int    g_is64;

// ---------------------------------------------------------------------------
// Kernel A: collapse both layers into the gap direction (block-per-row).
//   dA[i] = sum_k W1[i][k]     * (W2[k][0]-W2[k][1])   i in [0,128)
//   dB[i] = sum_k W1[128+i][k] * (W2[k][0]-W2[k][1])
//   block 256: gap bias;  block 257: edge dtype probe.
// Implicit PDL trigger at block exit -> node blocks dispatch during drain.
// ---------------------------------------------------------------------------
__global__ void __launch_bounds__(256) combine_kernel(
        const float* __restrict__ W1, const float* __restrict__ b1,
        const float* __restrict__ W2, const float* __restrict__ b2,
        const long long* __restrict__ edges_as_i64, int n_edges)
{
    __shared__ float red[8];
    int b    = blockIdx.x;
    int tid  = threadIdx.x;
    int warp = tid >> 5;
    int lane = tid & 31;

    if (b < 257) {
        float w0 = W2[2 * tid]         - W2[2 * tid + 1];
        float w1 = W2[2 * (tid + 256)] - W2[2 * (tid + 256) + 1];
        const float* row = (b < 256) ? (W1 + (size_t)b * (4 * HIDDEN)) : b1;
        float acc = row[tid] * w0 + row[tid + 256] * w1;

        #pragma unroll
        for (int o = 16; o; o >>= 1) acc += __shfl_xor_sync(0xffffffffu, acc, o);
        if (lane == 0) red[warp] = acc;
        __syncthreads();
        if (warp == 0) {
            float v = (lane < 8) ? red[lane] : 0.f;
            #pragma unroll
            for (int o = 4; o; o >>= 1) v += __shfl_xor_sync(0xffffffffu, v, o);
            if (lane == 0) {
                if (b < HIDDEN)   ((float*)g_dAv)[b] = v;
                else if (b < 256) ((float*)g_dBv)[b - HIDDEN] = v;
                else              g_gapb = v + b2[0] - b2[1];
            }
        }
    } else if (warp == 0) {
        // Dtype probe: an int32 buffer misread as int64 pairs fails the
        // [0, MAX_NODES) range check almost surely over 64 samples.
        int ok = 1;
        #pragma unroll
        for (int r = 0; r < 2; ++r) {
            int t = r * 32 + lane;
            if (t < n_edges) {
                long long v = edges_as_i64[t];
                if (v < 0 || v >= (long long)MAX_NODES) ok = 0;
            }
        }
        ok = __all_sync(0xffffffffu, ok);
        if (lane == 0) g_is64 = ok;
    }
}

// ---------------------------------------------------------------------------
// Kernel B (PDL secondary): per-node gap projections. Feature loads issued
// BEFORE cudaGridDependencySynchronize() — the 51.2 MB stream starts while
// combine drains; the HW wait replaces any flag protocol. Triggers the edge
// kernel's dispatch right after the sync so edge's index streaming overlaps
// this kernel's execution/tail.
// ---------------------------------------------------------------------------
#define NODES_PER_WARP  8
#define WARPS_PER_BLOCK 8
#define NODES_PER_BLOCK (NODES_PER_WARP * WARPS_PER_BLOCK)   // 64

__global__ void __launch_bounds__(256) node_kernel(const float* __restrict__ feat,
                                                   int n_nodes)
{
    int warp = threadIdx.x >> 5;
    int lane = threadIdx.x & 31;
    int node0 = blockIdx.x * NODES_PER_BLOCK + warp * NODES_PER_WARP;

    // Independent pre-sync work: front-batched feature row loads (MLP=8).
    float4 x[NODES_PER_WARP];
    #pragma unroll
    for (int r = 0; r < NODES_PER_WARP; ++r) {
        int node = node0 + r;
        if (node < n_nodes)
            x[r] = reinterpret_cast<const float4*>(feat + (size_t)node * HIDDEN)[lane];
    }

    cudaGridDependencySynchronize();           // wait: combine results visible
    cudaTriggerProgrammaticLaunchCompletion(); // let edge blocks dispatch early

    float4 wa = g_dAv[lane];
    float4 wb = g_dBv[lane];

    #pragma unroll
    for (int r = 0; r < NODES_PER_WARP; ++r) {
        int node = node0 + r;
        if (node >= n_nodes) break;
        float gs = x[r].x * wa.x + x[r].y * wa.y + x[r].z * wa.z + x[r].w * wa.w;
        float gd = x[r].x * wb.x + x[r].y * wb.y + x[r].z * wb.z + x[r].w * wb.w;
        #pragma unroll
        for (int o = 16; o; o >>= 1) {
            gs += __shfl_xor_sync(0xffffffffu, gs, o);
            gd += __shfl_xor_sync(0xffffffffu, gd, o);
        }
        if (lane == 0) {
            g_GS[node] = gs;
            g_GD[node] = gd;
        }
    }
}

// ---------------------------------------------------------------------------
// Kernel C (PDL secondary): 2 edges/thread. Index loads + combine-produced
// scalars are read PRE-sync (combine's grid completed before node launched,
// so its writes are flushed/visible; indices come from the input buffer).
// Post-sync: 4B gathers from the two 400 KB L2-resident tables + sigmoid.
// ---------------------------------------------------------------------------
__global__ void __launch_bounds__(256) edge_kernel(const void* __restrict__ edges,
                                                   float2* __restrict__ out,
                                                   int n_edges)
{
    int t = blockIdx.x * blockDim.x + threadIdx.x;
    int base = t * 2;
    bool full = (base + 2 <= n_edges);
    bool tail = !full && (base < n_edges);     // odd last edge

    // ---- Pre-sync independent work ----
    float gapb = g_gapb;                        // produced by combine (visible)
    int   is64 = g_is64;
    int s0 = 0, s1 = 0, d0 = 0, d1 = 0;

    if (full) {
        if (is64) {
            const longlong2* E = (const longlong2*)edges;
            longlong2 s = E[base >> 1];
            longlong2 d = E[(n_edges + base) >> 1];   // n_edges even on this path
            s0 = (int)s.x; s1 = (int)s.y; d0 = (int)d.x; d1 = (int)d.y;
        } else {
            const int2* E = (const int2*)edges;
            int2 s = E[base >> 1];
            int2 d = E[(n_edges + base) >> 1];
            s0 = s.x; s1 = s.y; d0 = d.x; d1 = d.y;
        }
    } else if (tail) {
        int e = n_edges - 1;
        if (is64) {
            const long long* E = (const long long*)edges;
            s0 = (int)E[e]; d0 = (int)E[e + n_edges];
        } else {
            const int* E = (const int*)edges;
            s0 = E[e]; d0 = E[e + n_edges];
        }
    }

    cudaGridDependencySynchronize();            // wait: g_GS/g_GD visible

    // ---- Post-sync: gathers + sigmoid of the logit gap ----
    if (full) {
        float gs0 = __ldg(&g_GS[s0]);
        float gs1 = __ldg(&g_GS[s1]);
        float gd0 = __ldg(&g_GD[d0]);
        float gd1 = __ldg(&g_GD[d1]);

        float p0 = 1.0f / (1.0f + __expf(gs0 + gd0 + gapb));
        float p1 = 1.0f / (1.0f + __expf(gs1 + gd1 + gapb));

        *(float4*)(out + base) = make_float4(1.0f - p0, p0, 1.0f - p1, p1);
    } else if (tail) {
        float p = 1.0f / (1.0f + __expf(__ldg(&g_GS[s0]) + __ldg(&g_GD[d0]) + gapb));
        out[n_edges - 1] = make_float2(1.0f - p, p);
    }
}

// ---------------------------------------------------------------------------
// Launch: combine -> node -> edge, with PDL on node and edge so block
// dispatch overlaps the predecessor's drain. metadata order:
//   0: node_features_after_gcn (float32, N_NODES*128)
//   1: edges                   (int64 or int32, 2*N_EDGES)
//   2: W1 (256*512)  3: b1 (512)  4: W2 (512*2)  5: b2 (2)
// ---------------------------------------------------------------------------
extern "C" void kernel_launch(void* const* d_in, const int* in_sizes, int n_in,
                              void* d_out, int out_size)
{
    const float* feat  = (const float*)d_in[0];
    const void*  edges = d_in[1];
    const float* W1    = (const float*)d_in[2];
    const float* b1    = (const float*)d_in[3];
    const float* W2    = (const float*)d_in[4];
    const float* b2    = (const float*)d_in[5];

    int n_nodes = in_sizes[0] / HIDDEN;
    if (n_nodes > MAX_NODES) n_nodes = MAX_NODES;
    int n_edges = in_sizes[1] / 2;

    // A: plain launch (first kernel eats the ramp regardless).
    combine_kernel<<<258, 256>>>(W1, b1, W2, b2, (const long long*)edges, n_edges);

    cudaLaunchAttribute pdl[1];
    pdl[0].id = cudaLaunchAttributeProgrammaticStreamSerialization;
    pdl[0].val.programmaticStreamSerializationAllowed = 1;

    // B: node projections (PDL secondary of combine).
    {
        cudaLaunchConfig_t cfg = {};
        cfg.gridDim  = dim3((n_nodes + NODES_PER_BLOCK - 1) / NODES_PER_BLOCK, 1, 1);
        cfg.blockDim = dim3(256, 1, 1);
        cfg.stream   = 0;
        cfg.attrs    = pdl;
        cfg.numAttrs = 1;
        cudaLaunchKernelEx(&cfg, node_kernel, feat, n_nodes);
    }

    // C: edge gather + sigmoid (PDL secondary of node).
    {
        int nthreads = (n_edges + 1) / 2;
        cudaLaunchConfig_t cfg = {};
        cfg.gridDim  = dim3((nthreads + 255) / 256, 1, 1);
        cfg.blockDim = dim3(256, 1, 1);
        cfg.stream   = 0;
        cfg.attrs    = pdl;
        cfg.numAttrs = 1;
        cudaLaunchKernelEx(&cfg, edge_kernel, edges, (float2*)d_out, n_edges);
    }
}

// round 17
// speedup vs baseline: 1.2119x; 1.0153x over previous
#include <cuda_runtime.h>

#define HIDDEN    128
#define MAX_NODES 100000

// Scratch (device globals; allocation is forbidden).
// Gap form: softmax over 2 classes depends only on l0-l1, so per node keep
//   gs[n] = n·dA,  gd[n] = n·dB,  dA/dB = W1 halves @ (w2_0 - w2_1).
__device__ float  g_GS[MAX_NODES];
__device__ float  g_GD[MAX_NODES];
__device__ float4 g_dAv[32], g_dBv[32];   // dA, dB as 32 x float4
__device__ float  g_gapb;                 // b1·(w2_0-w2_1) + b2_0 - b2_1
__device__ int    g_is64;

// ---------------------------------------------------------------------------
// Kernel A: collapse both layers into the gap direction (block-per-row).
// TRIGGERS ITS PDL COMPLETION IMMEDIATELY: node blocks may dispatch and
// stream features concurrently — node only reads our output after its
// cudaGridDependencySynchronize(), which waits for this grid's FULL
// completion (visibility guaranteed). This hides combine's entire duration
// under node's 51.2 MB load front.
//   dA[i] = sum_k W1[i][k]     * (W2[k][0]-W2[k][1])   i in [0,128)
//   dB[i] = sum_k W1[128+i][k] * (W2[k][0]-W2[k][1])
//   block 256: gap bias;  block 257: edge dtype probe.
// ---------------------------------------------------------------------------
__global__ void __launch_bounds__(256) combine_kernel(
        const float* __restrict__ W1, const float* __restrict__ b1,
        const float* __restrict__ W2, const float* __restrict__ b2,
        const long long* __restrict__ edges_as_i64, int n_edges)
{
    cudaTriggerProgrammaticLaunchCompletion();   // release node dispatch NOW

    __shared__ float red[8];
    int b    = blockIdx.x;
    int tid  = threadIdx.x;
    int warp = tid >> 5;
    int lane = tid & 31;

    if (b < 257) {
        float w0 = W2[2 * tid]         - W2[2 * tid + 1];
        float w1 = W2[2 * (tid + 256)] - W2[2 * (tid + 256) + 1];
        const float* row = (b < 256) ? (W1 + (size_t)b * (4 * HIDDEN)) : b1;
        float acc = row[tid] * w0 + row[tid + 256] * w1;

        #pragma unroll
        for (int o = 16; o; o >>= 1) acc += __shfl_xor_sync(0xffffffffu, acc, o);
        if (lane == 0) red[warp] = acc;
        __syncthreads();
        if (warp == 0) {
            float v = (lane < 8) ? red[lane] : 0.f;
            #pragma unroll
            for (int o = 4; o; o >>= 1) v += __shfl_xor_sync(0xffffffffu, v, o);
            if (lane == 0) {
                if (b < HIDDEN)   ((float*)g_dAv)[b] = v;
                else if (b < 256) ((float*)g_dBv)[b - HIDDEN] = v;
                else              g_gapb = v + b2[0] - b2[1];
            }
        }
    } else if (warp == 0) {
        // Dtype probe: an int32 buffer misread as int64 pairs fails the
        // [0, MAX_NODES) range check almost surely over 64 samples.
        int ok = 1;
        #pragma unroll
        for (int r = 0; r < 2; ++r) {
            int t = r * 32 + lane;
            if (t < n_edges) {
                long long v = edges_as_i64[t];
                if (v < 0 || v >= (long long)MAX_NODES) ok = 0;
            }
        }
        ok = __all_sync(0xffffffffu, ok);
        if (lane == 0) g_is64 = ok;
    }
}

// ---------------------------------------------------------------------------
// Kernel B (PDL secondary of combine): per-node gap projections. Feature
// loads are issued BEFORE cudaGridDependencySynchronize() — with combine's
// early trigger, the 51.2 MB stream now overlaps combine's whole execution.
// Triggers edge dispatch right after the sync so edge streams its indices
// during this kernel's compute phase.
// ---------------------------------------------------------------------------
#define NODES_PER_WARP  8
#define WARPS_PER_BLOCK 8
#define NODES_PER_BLOCK (NODES_PER_WARP * WARPS_PER_BLOCK)   // 64

__global__ void __launch_bounds__(256) node_kernel(const float* __restrict__ feat,
                                                   int n_nodes)
{
    int warp = threadIdx.x >> 5;
    int lane = threadIdx.x & 31;
    int node0 = blockIdx.x * NODES_PER_BLOCK + warp * NODES_PER_WARP;

    // Independent pre-sync work: front-batched feature row loads (MLP=8).
    float4 x[NODES_PER_WARP];
    #pragma unroll
    for (int r = 0; r < NODES_PER_WARP; ++r) {
        int node = node0 + r;
        if (node < n_nodes)
            x[r] = reinterpret_cast<const float4*>(feat + (size_t)node * HIDDEN)[lane];
    }

    cudaGridDependencySynchronize();           // combine grid complete + visible
    cudaTriggerProgrammaticLaunchCompletion(); // let edge blocks dispatch early

    float4 wa = g_dAv[lane];
    float4 wb = g_dBv[lane];

    #pragma unroll
    for (int r = 0; r < NODES_PER_WARP; ++r) {
        int node = node0 + r;
        if (node >= n_nodes) break;
        float gs = x[r].x * wa.x + x[r].y * wa.y + x[r].z * wa.z + x[r].w * wa.w;
        float gd = x[r].x * wb.x + x[r].y * wb.y + x[r].z * wb.z + x[r].w * wb.w;
        #pragma unroll
        for (int o = 16; o; o >>= 1) {
            gs += __shfl_xor_sync(0xffffffffu, gs, o);
            gd += __shfl_xor_sync(0xffffffffu, gd, o);
        }
        if (lane == 0) {
            g_GS[node] = gs;
            g_GD[node] = gd;
        }
    }
}

// ---------------------------------------------------------------------------
// Kernel C (PDL secondary of node): 2 edges/thread. Index loads and the
// combine-produced scalars are read PRE-sync (edge dispatches only after
// node's trigger, which is after node's grid-sync => combine is complete).
// Post-sync: 4B gathers from the two 400 KB L2-resident tables + sigmoid.
// ---------------------------------------------------------------------------
__global__ void __launch_bounds__(256) edge_kernel(const void* __restrict__ edges,
                                                   float2* __restrict__ out,
                                                   int n_edges)
{
    int t = blockIdx.x * blockDim.x + threadIdx.x;
    int base = t * 2;
    bool full = (base + 2 <= n_edges);
    bool tail = !full && (base < n_edges);     // odd last edge

    // ---- Pre-sync independent work ----
    float gapb = g_gapb;                        // combine complete (see above)
    int   is64 = g_is64;
    int s0 = 0, s1 = 0, d0 = 0, d1 = 0;

    if (full) {
        if (is64) {
            const longlong2* E = (const longlong2*)edges;
            longlong2 s = E[base >> 1];
            longlong2 d = E[(n_edges + base) >> 1];   // n_edges even on this path
            s0 = (int)s.x; s1 = (int)s.y; d0 = (int)d.x; d1 = (int)d.y;
        } else {
            const int2* E = (const int2*)edges;
            int2 s = E[base >> 1];
            int2 d = E[(n_edges + base) >> 1];
            s0 = s.x; s1 = s.y; d0 = d.x; d1 = d.y;
        }
    } else if (tail) {
        int e = n_edges - 1;
        if (is64) {
            const long long* E = (const long long*)edges;
            s0 = (int)E[e]; d0 = (int)E[e + n_edges];
        } else {
            const int* E = (const int*)edges;
            s0 = E[e]; d0 = E[e + n_edges];
        }
    }

    cudaGridDependencySynchronize();            // node grid complete: GS/GD visible

    // ---- Post-sync: gathers + sigmoid of the logit gap ----
    if (full) {
        float gs0 = __ldg(&g_GS[s0]);
        float gs1 = __ldg(&g_GS[s1]);
        float gd0 = __ldg(&g_GD[d0]);
        float gd1 = __ldg(&g_GD[d1]);

        float p0 = 1.0f / (1.0f + __expf(gs0 + gd0 + gapb));
        float p1 = 1.0f / (1.0f + __expf(gs1 + gd1 + gapb));

        *(float4*)(out + base) = make_float4(1.0f - p0, p0, 1.0f - p1, p1);
    } else if (tail) {
        float p = 1.0f / (1.0f + __expf(__ldg(&g_GS[s0]) + __ldg(&g_GD[d0]) + gapb));
        out[n_edges - 1] = make_float2(1.0f - p, p);
    }
}

// ---------------------------------------------------------------------------
// Launch: combine -> node -> edge, PDL-chained. metadata order:
//   0: node_features_after_gcn (float32, N_NODES*128)
//   1: edges                   (int64 or int32, 2*N_EDGES)
//   2: W1 (256*512)  3: b1 (512)  4: W2 (512*2)  5: b2 (2)
// ---------------------------------------------------------------------------
extern "C" void kernel_launch(void* const* d_in, const int* in_sizes, int n_in,
                              void* d_out, int out_size)
{
    const float* feat  = (const float*)d_in[0];
    const void*  edges = d_in[1];
    const float* W1    = (const float*)d_in[2];
    const float* b1    = (const float*)d_in[3];
    const float* W2    = (const float*)d_in[4];
    const float* b2    = (const float*)d_in[5];

    int n_nodes = in_sizes[0] / HIDDEN;
    if (n_nodes > MAX_NODES) n_nodes = MAX_NODES;
    int n_edges = in_sizes[1] / 2;

    // A: combine (triggers its PDL completion at entry).
    combine_kernel<<<258, 256>>>(W1, b1, W2, b2, (const long long*)edges, n_edges);

    cudaLaunchAttribute pdl[1];
    pdl[0].id = cudaLaunchAttributeProgrammaticStreamSerialization;
    pdl[0].val.programmaticStreamSerializationAllowed = 1;

    // B: node projections (PDL secondary of combine — dispatches immediately).
    {
        cudaLaunchConfig_t cfg = {};
        cfg.gridDim  = dim3((n_nodes + NODES_PER_BLOCK - 1) / NODES_PER_BLOCK, 1, 1);
        cfg.blockDim = dim3(256, 1, 1);
        cfg.stream   = 0;
        cfg.attrs    = pdl;
        cfg.numAttrs = 1;
        cudaLaunchKernelEx(&cfg, node_kernel, feat, n_nodes);
    }

    // C: edge gather + sigmoid (PDL secondary of node).
    {
        int nthreads = (n_edges + 1) / 2;
        cudaLaunchConfig_t cfg = {};
        cfg.gridDim  = dim3((nthreads + 255) / 256, 1, 1);
        cfg.blockDim = dim3(256, 1, 1);
        cfg.stream   = 0;
        cfg.attrs    = pdl;
        cfg.numAttrs = 1;
        cudaLaunchKernelEx(&cfg, edge_kernel, edges, (float2*)d_out, n_edges);
    }
}